// round 17
// baseline (speedup 1.0000x reference)
#include <cuda_runtime.h>
#include <cuda_bf16.h>
#include <math.h>
#include <float.h>
#include <stdint.h>

// Problem constants
#define BATCH   2
#define SEQ     2048
#define HID     2048
#define NHEADS  16
#define NKV     4
#define HDIM    256
#define QKDIM   (NHEADS*HDIM)   // 4096
#define KVDIM   (NKV*HDIM)      // 1024

// ---------------- scratch (device globals) ---------------------------------
__device__ float g_q[BATCH*NHEADS*SEQ*HDIM];   // [b,h,s,d]
__device__ float g_k[BATCH*NKV*SEQ*HDIM];      // [b,kv,s,d]
__device__ float g_v[BATCH*NKV*SEQ*HDIM];
__device__ float g_attn[BATCH*SEQ*QKDIM];      // [b,s,h*d]

// ---------------- tf32 / mma / cp.async helpers ----------------------------
__device__ __forceinline__ float f2tf32(float x)
{
    uint32_t r;
    asm("cvt.rna.tf32.f32 %0, %1;" : "=r"(r) : "f"(x));
    return __uint_as_float(r);
}

__device__ __forceinline__ uint32_t f2tf32b(float x)
{
    uint32_t r;
    asm("cvt.rna.tf32.f32 %0, %1;" : "=r"(r) : "f"(x));
    return r;
}

__device__ __forceinline__ void mma_tf32(float* c, const uint32_t* a, const uint32_t* b)
{
    asm volatile(
        "mma.sync.aligned.m16n8k8.row.col.f32.tf32.tf32.f32 "
        "{%0,%1,%2,%3}, {%4,%5,%6,%7}, {%8,%9}, {%0,%1,%2,%3};"
        : "+f"(c[0]), "+f"(c[1]), "+f"(c[2]), "+f"(c[3])
        : "r"(a[0]), "r"(a[1]), "r"(a[2]), "r"(a[3]), "r"(b[0]), "r"(b[1]));
}

__device__ __forceinline__ void cp_async16(float* smem_dst, const float* gmem_src)
{
    uint32_t s = (uint32_t)__cvta_generic_to_shared(smem_dst);
    asm volatile("cp.async.cg.shared.global [%0], [%1], 16;" :: "r"(s), "l"(gmem_src));
}

// ---------------- tf32 GEMM core: double-buffered cp.async, BK=32 ----------
// Block 128x128, 256 threads = 8 warps (4m x 2n), warp tile 32x64.
#define BK2   32
#define ASTR2 36
#define BSTR2 136
#define A_TILE (128 * ASTR2)   // 4608 floats
#define B_TILE (32 * BSTR2)    // 4352 floats
#define TG_SMEM ((2 * A_TILE + 2 * B_TILE) * 4)   // 71680 bytes

__device__ __forceinline__ void gemm_core(
    const float* __restrict__ A, const float* __restrict__ B,
    float* __restrict__ C, int N, int K, int mode, int bm, int bn,
    float* dsm)
{
    float* Asm[2] = { dsm, dsm + A_TILE };
    float* Bsm[2] = { dsm + 2 * A_TILE, dsm + 2 * A_TILE + B_TILE };

    const int tid = threadIdx.x;
    const int wid  = tid >> 5;
    const int lane = tid & 31;
    const int g = lane >> 2;
    const int t = lane & 3;
    const int wm = (wid & 3) * 32;
    const int wn = (wid >> 2) * 64;

    float acc[2][8][4];
#pragma unroll
    for (int i = 0; i < 2; i++)
#pragma unroll
        for (int j = 0; j < 8; j++)
#pragma unroll
            for (int c = 0; c < 4; c++) acc[i][j][c] = 0.f;

    // A tile: 128x32 = 1024 float4; B tile: 32x128 = 1024 float4; 4 each/thread
#define LOAD_TILES(k0, buf)                                               \
    {                                                                     \
        _Pragma("unroll")                                                 \
        for (int i = 0; i < 4; i++) {                                     \
            const int c = tid + i * 256;                                  \
            const int ar = c >> 3, ac4 = (c & 7) * 4;                     \
            cp_async16(&Asm[buf][ar * ASTR2 + ac4],                       \
                       &A[(size_t)(bm + ar) * K + (k0) + ac4]);           \
            const int br = c >> 5, bc4 = (c & 31) * 4;                    \
            cp_async16(&Bsm[buf][br * BSTR2 + bc4],                       \
                       &B[(size_t)((k0) + br) * N + bn + bc4]);           \
        }                                                                 \
    }

    LOAD_TILES(0, 0);
    asm volatile("cp.async.commit_group;");

    int buf = 0;
    for (int k0 = 0; k0 < K; k0 += BK2, buf ^= 1) {
        const bool has_next = (k0 + BK2 < K);
        if (has_next) {
            LOAD_TILES(k0 + BK2, buf ^ 1);
            asm volatile("cp.async.commit_group;");
            asm volatile("cp.async.wait_group 1;");
        } else {
            asm volatile("cp.async.wait_group 0;");
        }
        __syncthreads();

        const float* As = Asm[buf];
        const float* Bs = Bsm[buf];
#pragma unroll
        for (int kk = 0; kk < BK2; kk += 8) {
            uint32_t afr[2][4];
#pragma unroll
            for (int mt = 0; mt < 2; mt++) {
                const int m0 = wm + mt * 16;
                afr[mt][0] = f2tf32b(As[(m0 + g) * ASTR2 + kk + t]);
                afr[mt][1] = f2tf32b(As[(m0 + g + 8) * ASTR2 + kk + t]);
                afr[mt][2] = f2tf32b(As[(m0 + g) * ASTR2 + kk + t + 4]);
                afr[mt][3] = f2tf32b(As[(m0 + g + 8) * ASTR2 + kk + t + 4]);
            }
            uint32_t bfr[8][2];
#pragma unroll
            for (int nt = 0; nt < 8; nt++) {
                const int n0 = wn + nt * 8;
                bfr[nt][0] = f2tf32b(Bs[(kk + t) * BSTR2 + n0 + g]);
                bfr[nt][1] = f2tf32b(Bs[(kk + t + 4) * BSTR2 + n0 + g]);
            }
#pragma unroll
            for (int mt = 0; mt < 2; mt++)
#pragma unroll
                for (int nt = 0; nt < 8; nt++)
                    mma_tf32(acc[mt][nt], afr[mt], bfr[nt]);
        }
        __syncthreads();
    }
#undef LOAD_TILES

    // epilogue (verified mapping)
#pragma unroll
    for (int mt = 0; mt < 2; mt++) {
#pragma unroll
        for (int nt = 0; nt < 8; nt++) {
#pragma unroll
            for (int half = 0; half < 2; half++) {
                const int m = bm + wm + mt * 16 + g + half * 8;
                const int n = bn + wn + nt * 8 + 2 * t;
                const float v0 = acc[mt][nt][half * 2 + 0];
                const float v1 = acc[mt][nt][half * 2 + 1];
                if (mode == 0) {
                    C[(size_t)m * N + n]     = v0;
                    C[(size_t)m * N + n + 1] = v1;
                } else if (mode == 1) {
                    const int bb = m >> 11, s = m & 2047;
                    const int h = n >> 8,  d = n & 255;
                    float* p = &C[(((size_t)(bb*NHEADS + h))*SEQ + s)*HDIM + d];
                    p[0] = v0; p[1] = v1;
                } else {
                    const int bb = m >> 11, s = m & 2047;
                    const int h = n >> 8,  d = n & 255;
                    float* p = &C[(((size_t)(bb*NKV + h))*SEQ + s)*HDIM + d];
                    p[0] = v0; p[1] = v1;
                }
            }
        }
    }
}

// Fused QKV projection: grid (48, 32). bx<32: Q; 32..39: K; 40..47: V.
__global__ __launch_bounds__(256, 2) void qkv_kernel(
    const float* __restrict__ hidden, const float* __restrict__ Wq,
    const float* __restrict__ Wk, const float* __restrict__ Wv)
{
    extern __shared__ float dsm[];
    const int bx = blockIdx.x;
    const int bm = blockIdx.y * 128;
    if (bx < 32)
        gemm_core(hidden, Wq, g_q, QKDIM, HID, 1, bm, bx * 128, dsm);
    else if (bx < 40)
        gemm_core(hidden, Wk, g_k, KVDIM, HID, 2, bm, (bx - 32) * 128, dsm);
    else
        gemm_core(hidden, Wv, g_v, KVDIM, HID, 2, bm, (bx - 40) * 128, dsm);
}

// Output projection: C = attn @ Wo (mode 0)
__global__ __launch_bounds__(256, 2) void oproj_kernel(
    const float* __restrict__ Wo, float* __restrict__ out)
{
    extern __shared__ float dsm[];
    gemm_core(g_attn, Wo, out, HID, QKDIM, 0, blockIdx.y * 128, blockIdx.x * 128, dsm);
}

// ---------------- RoPE (SIGN-FLIPPED, verified) ----------------------------
__global__ void rope_kernel(float* __restrict__ buf,
                            const int* __restrict__ pos_ids, int heads)
{
    const long total = (long)BATCH * heads * SEQ * 128;
    for (long idx = (long)blockIdx.x * blockDim.x + threadIdx.x; idx < total;
         idx += (long)gridDim.x * blockDim.x) {
        const int j = (int)(idx & 127);
        const int s = (int)((idx >> 7) & 2047);
        const long hh = idx >> 18;
        const long base = hh * ((long)SEQ * HDIM) + (long)s * HDIM;
        const int b = (int)(hh / heads);
        const float pos = (float)pos_ids[b * SEQ + s];
        const float invf = powf(10000.0f, -(float)j * (1.0f / 128.0f));
        float c, sn;
        sincosf(pos * invf, &c, &sn);
        const float x1 = buf[base + j];
        const float x2 = buf[base + j + 128];
        buf[base + j]       = x1 * c + x2 * sn;
        buf[base + j + 128] = x2 * c - x1 * sn;
    }
}

// ---------------- tensor-core flash attention (tf32, verified R14) ---------
#define QSTR 260
#define KSTR 260
#define VSTR 264
#define PSTR2 68

__global__ __launch_bounds__(256) void flash_tc_kernel(
    const float* __restrict__ Q, const float* __restrict__ K,
    const float* __restrict__ V, float* __restrict__ Out)
{
    extern __shared__ float sm[];
    float* Qs   = sm;
    float* Ks   = Qs + 64 * QSTR;
    float* Vs   = Ks + 64 * KSTR;
    float* Ps   = Vs + 64 * VSTR;
    float* sRed = Ps + 64 * PSTR2;
    float* sM   = sRed + 320;
    float* sL   = sM + 64;
    float* sC   = sL + 64;

    const int qb = blockIdx.x;
    const int h  = blockIdx.y;
    const int b  = blockIdx.z;
    const int kvh = h >> 2;

    const int tid  = threadIdx.x;
    const int wid  = tid >> 5;
    const int lane = tid & 31;
    const int g = lane >> 2;
    const int t = lane & 3;
    const int wm  = (wid & 3) * 16;
    const int wnS = (wid >> 2) * 32;
    const int wnO = (wid >> 2) * 128;

    const float* Qg = Q + (((size_t)(b*NHEADS + h))*SEQ + qb*64) * HDIM;
    const float* Kg = K + ((size_t)(b*NKV + kvh))*SEQ * HDIM;
    const float* Vg = V + ((size_t)(b*NKV + kvh))*SEQ * HDIM;

    for (int i = tid; i < 64 * 64; i += 256) {
        const int r = i >> 6;
        const int c = (i & 63) * 4;
        float4 v = *(const float4*)&Qg[r * HDIM + c];
        float* p = &Qs[r * QSTR + c];
        p[0] = f2tf32(v.x); p[1] = f2tf32(v.y); p[2] = f2tf32(v.z); p[3] = f2tf32(v.w);
    }
    if (tid < 64) { sM[tid] = -3.0e38f; sL[tid] = 0.f; }

    float oacc[16][4];
#pragma unroll
    for (int nt = 0; nt < 16; nt++)
#pragma unroll
        for (int c = 0; c < 4; c++) oacc[nt][c] = 0.f;

    const int row_q = tid >> 2;
    const int qtr   = tid & 3;

    for (int kb = 0; kb <= qb; kb++) {
        __syncthreads();
        for (int i = tid; i < 64 * 64; i += 256) {
            const int r = i >> 6;
            const int c = (i & 63) * 4;
            float4 v = *(const float4*)&Kg[((size_t)(kb*64 + r)) * HDIM + c];
            float* p = &Ks[r * KSTR + c];
            p[0] = f2tf32(v.x); p[1] = f2tf32(v.y); p[2] = f2tf32(v.z); p[3] = f2tf32(v.w);
            v = *(const float4*)&Vg[((size_t)(kb*64 + r)) * HDIM + c];
            p = &Vs[r * VSTR + c];
            p[0] = f2tf32(v.x); p[1] = f2tf32(v.y); p[2] = f2tf32(v.z); p[3] = f2tf32(v.w);
        }
        __syncthreads();

        float sacc[4][4];
#pragma unroll
        for (int nt = 0; nt < 4; nt++)
#pragma unroll
            for (int c = 0; c < 4; c++) sacc[nt][c] = 0.f;

#pragma unroll 4
        for (int d = 0; d < HDIM; d += 8) {
            uint32_t af[4];
            af[0] = __float_as_uint(Qs[(wm + g) * QSTR + d + t]);
            af[1] = __float_as_uint(Qs[(wm + g + 8) * QSTR + d + t]);
            af[2] = __float_as_uint(Qs[(wm + g) * QSTR + d + t + 4]);
            af[3] = __float_as_uint(Qs[(wm + g + 8) * QSTR + d + t + 4]);
            uint32_t bf[4][2];
#pragma unroll
            for (int nt = 0; nt < 4; nt++) {
                const int n0 = wnS + nt * 8;
                bf[nt][0] = __float_as_uint(Ks[(n0 + g) * KSTR + d + t]);
                bf[nt][1] = __float_as_uint(Ks[(n0 + g) * KSTR + d + t + 4]);
            }
#pragma unroll
            for (int nt = 0; nt < 4; nt++)
                mma_tf32(sacc[nt], af, bf[nt]);
        }

        const bool diag = (kb == qb);
#pragma unroll
        for (int nt = 0; nt < 4; nt++) {
#pragma unroll
            for (int half = 0; half < 2; half++) {
                const int row = wm + g + half * 8;
                const int col = wnS + nt * 8 + 2 * t;
                const int qidx = qb * 64 + row;
                const int kidx = kb * 64 + col;
                float v0 = sacc[nt][half * 2 + 0] * 0.0625f;
                float v1 = sacc[nt][half * 2 + 1] * 0.0625f;
                if (diag) {
                    if (kidx > qidx)     v0 += -1e9f;
                    if (kidx + 1 > qidx) v1 += -1e9f;
                }
                Ps[row * PSTR2 + col]     = v0;
                Ps[row * PSTR2 + col + 1] = v1;
            }
        }
        __syncthreads();

        {
            float pm = -3.0e38f;
            const int base = row_q * PSTR2 + qtr * 16;
#pragma unroll
            for (int j = 0; j < 16; j++) pm = fmaxf(pm, Ps[base + j]);
            sRed[row_q * 5 + qtr] = pm;
        }
        __syncthreads();

        if (tid < 64) {
            float rm = fmaxf(fmaxf(sRed[tid*5+0], sRed[tid*5+1]),
                             fmaxf(sRed[tid*5+2], sRed[tid*5+3]));
            const float mold = sM[tid];
            const float mnew = fmaxf(mold, rm);
            sC[tid] = expf(mold - mnew);
            sM[tid] = mnew;
        }
        __syncthreads();

        {
            const float mnew = sM[row_q];
            const int base = row_q * PSTR2 + qtr * 16;
            float ps = 0.f;
#pragma unroll
            for (int j = 0; j < 16; j++) {
                const float p = expf(Ps[base + j] - mnew);
                Ps[base + j] = f2tf32(p);
                ps += p;
            }
            sRed[row_q * 5 + qtr] = ps;
        }
        {
            const float corr0 = sC[wm + g];
            const float corr1 = sC[wm + g + 8];
#pragma unroll
            for (int nt = 0; nt < 16; nt++) {
                oacc[nt][0] *= corr0; oacc[nt][1] *= corr0;
                oacc[nt][2] *= corr1; oacc[nt][3] *= corr1;
            }
        }
        __syncthreads();

        if (tid < 64) {
            const float rs = sRed[tid*5+0] + sRed[tid*5+1]
                           + sRed[tid*5+2] + sRed[tid*5+3];
            sL[tid] = sL[tid] * sC[tid] + rs;
        }

#pragma unroll
        for (int kk = 0; kk < 64; kk += 8) {
            uint32_t af[4];
            af[0] = __float_as_uint(Ps[(wm + g) * PSTR2 + kk + t]);
            af[1] = __float_as_uint(Ps[(wm + g + 8) * PSTR2 + kk + t]);
            af[2] = __float_as_uint(Ps[(wm + g) * PSTR2 + kk + t + 4]);
            af[3] = __float_as_uint(Ps[(wm + g + 8) * PSTR2 + kk + t + 4]);
#pragma unroll
            for (int nt = 0; nt < 16; nt++) {
                const int n0 = wnO + nt * 8;
                uint32_t bf[2];
                bf[0] = __float_as_uint(Vs[(kk + t) * VSTR + n0 + g]);
                bf[1] = __float_as_uint(Vs[(kk + t + 4) * VSTR + n0 + g]);
                mma_tf32(oacc[nt], af, bf);
            }
        }
    }
    __syncthreads();

    {
        const float inv0 = 1.0f / sL[wm + g];
        const float inv1 = 1.0f / sL[wm + g + 8];
        const int row0 = qb * 64 + wm + g;
        const int row1 = row0 + 8;
        float* o0 = Out + ((size_t)(b*SEQ + row0)) * QKDIM + h * HDIM;
        float* o1 = Out + ((size_t)(b*SEQ + row1)) * QKDIM + h * HDIM;
#pragma unroll
        for (int nt = 0; nt < 16; nt++) {
            const int col = wnO + nt * 8 + 2 * t;
            o0[col]     = oacc[nt][0] * inv0;
            o0[col + 1] = oacc[nt][1] * inv0;
            o1[col]     = oacc[nt][2] * inv1;
            o1[col + 1] = oacc[nt][3] * inv1;
        }
    }
}

// ---------------- launch ---------------------------------------------------
extern "C" void kernel_launch(void* const* d_in, const int* in_sizes, int n_in,
                              void* d_out, int out_size)
{
    const float* hidden = (const float*)d_in[0];
    const int*   pos    = (const int*)d_in[2];
    const float* Wq     = (const float*)d_in[3];
    const float* Wk     = (const float*)d_in[4];
    const float* Wv     = (const float*)d_in[5];
    const float* Wo     = (const float*)d_in[6];
    float* out = (float*)d_out;

    float *qb, *kb, *vb, *ab;
    cudaGetSymbolAddress((void**)&qb, g_q);
    cudaGetSymbolAddress((void**)&kb, g_k);
    cudaGetSymbolAddress((void**)&vb, g_v);
    cudaGetSymbolAddress((void**)&ab, g_attn);

    // Fused QKV projection (2 blocks/SM via launch bounds)
    cudaFuncSetAttribute(qkv_kernel,
                         cudaFuncAttributeMaxDynamicSharedMemorySize, TG_SMEM);
    cudaFuncSetAttribute(oproj_kernel,
                         cudaFuncAttributeMaxDynamicSharedMemorySize, TG_SMEM);
    qkv_kernel<<<dim3(48, 32), 256, TG_SMEM>>>(hidden, Wq, Wk, Wv);

    // RoPE (sign-flipped, verified)
    rope_kernel<<<2048, 256>>>(qb, pos, NHEADS);
    rope_kernel<<<2048, 256>>>(kb, pos, NKV);

    // tensor-core flash attention (verified R14)
    {
        const int smem = 55040 * (int)sizeof(float);
        cudaFuncSetAttribute(flash_tc_kernel,
                             cudaFuncAttributeMaxDynamicSharedMemorySize, smem);
        dim3 g(SEQ / 64, NHEADS, BATCH);
        flash_tc_kernel<<<g, 256, smem>>>(qb, kb, vb, ab);
    }

    // output projection -> d_out
    oproj_kernel<<<dim3(HID/128, SEQ*BATCH/128), 256, TG_SMEM>>>(Wo, out);
}